// round 1
// baseline (speedup 1.0000x reference)
#include <cuda_runtime.h>
#include <cstdint>

// Problem shape (fixed for this dataset entry)
#define B_    2
#define N_    50000
#define C_    64
#define M_    50000
#define K_    16
#define H_    8
#define CMID_ 16

// Runtime-detected index width flag (int64 vs int32), set by detect kernel.
__device__ int g_idx_is64;

// Detect whether neighbor_inds is int64: for int64 data with values < 2^31,
// every odd 32-bit word (high half) is zero. For int32 data, 256 consecutive
// index values being zero is probabilistically impossible (p ~ (2e-5)^256).
__global__ void detect_idx_kernel(const unsigned int* __restrict__ w) {
    if (threadIdx.x == 0 && blockIdx.x == 0) {
        int is64 = 1;
        #pragma unroll 1
        for (int i = 0; i < 256; i++) {
            if (w[2 * i + 1] != 0u) { is64 = 0; break; }
        }
        g_idx_is64 = is64;
    }
}

// One CTA (128 threads) per output point (b, m).
// Stage 1: gather 16 neighbor feature rows (64 f32 each) into SMEM with the
//          guidance scale fused in; load 16x16 weightnet into SMEM.
// Stage 2: thread t owns (c = t>>1, w-half = t&1): 8 outputs kept as four
//          packed f32x2 accumulators, updated with fma.rn.f32x2 (FFMA2),
//          halving FFMA-pipe pressure vs scalar FFMA.
// Stage 3: thread t writes 8 consecutive floats at t*8 -> the whole CTA
//          writes one contiguous 4KB block (pure STG.128, fully coalesced).
__global__ void __launch_bounds__(128)
pcf_kernel(const float* __restrict__ feat,
           const void*  __restrict__ inds_raw,
           const float* __restrict__ guid,
           const float* __restrict__ wn,
           float* __restrict__ out)
{
    __shared__ __align__(16) float sg[K_][C_];      // scaled gathered features
    __shared__ __align__(16) float swn[K_][CMID_];  // weightnet tile
    __shared__ int sidx[K_];

    const int p = blockIdx.x;       // point id in [0, B*M)
    const int b = p / M_;
    const int t = threadIdx.x;

    // --- neighbor indices (width-branch once per CTA) + weightnet tile ---
    if (t < K_) {
        long long idx;
        if (g_idx_is64) idx = ((const long long*)inds_raw)[(size_t)p * K_ + t];
        else            idx = (long long)((const int*)inds_raw)[(size_t)p * K_ + t];
        sidx[t] = (int)idx;
    }
    if (t < (K_ * CMID_ / 4)) {  // 64 float4 = 256 floats
        ((float4*)swn)[t] = ((const float4*)(wn + (size_t)p * (K_ * CMID_)))[t];
    }
    __syncthreads();

    // --- gather + guidance scaling: 256 float4 total, 2 per thread ---
    const float* fb = feat + (size_t)b * ((size_t)N_ * C_);
    const float* gp = guid + (size_t)p * (K_ * H_);
    #pragma unroll
    for (int i = 0; i < 2; i++) {
        int li = t + i * 128;        // 0..255
        int k  = li >> 4;            // 16 float4 per feature row
        int q  = li & 15;            // quad within row: channels 4q..4q+3
        float4 v = ((const float4*)(fb + (size_t)sidx[k] * C_))[q];
        float  s = gp[k * H_ + (q >> 1)];   // head = (4q)/8 = q>>1, const per quad
        v.x *= s; v.y *= s; v.z *= s; v.w *= s;
        ((float4*)(sg[k]))[q] = v;
    }
    __syncthreads();

    // --- per-point 64x16x16 contraction with packed f32x2 FMA ---
    const int c  = t >> 1;   // channel 0..63 (pairs of threads share c)
    const int wh = t & 1;    // which 8-wide half of the 16 w outputs

    unsigned long long a0 = 0ull, a1 = 0ull, a2 = 0ull, a3 = 0ull;
    #pragma unroll
    for (int k = 0; k < K_; k++) {
        float g = sg[k][c];                       // broadcast LDS (pair dedup)
        unsigned long long gg;
        asm("mov.b64 %0, {%1, %1};" : "=l"(gg) : "f"(g));
        const ulonglong2* row = (const ulonglong2*)(swn[k]);  // 64B row
        ulonglong2 L0 = row[wh * 2 + 0];          // w = wh*8 + 0..3  (LDS.128)
        ulonglong2 L1 = row[wh * 2 + 1];          // w = wh*8 + 4..7  (LDS.128)
        asm("fma.rn.f32x2 %0, %1, %2, %3;" : "=l"(a0) : "l"(gg), "l"(L0.x), "l"(a0));
        asm("fma.rn.f32x2 %0, %1, %2, %3;" : "=l"(a1) : "l"(gg), "l"(L0.y), "l"(a1));
        asm("fma.rn.f32x2 %0, %1, %2, %3;" : "=l"(a2) : "l"(gg), "l"(L1.x), "l"(a2));
        asm("fma.rn.f32x2 %0, %1, %2, %3;" : "=l"(a3) : "l"(gg), "l"(L1.y), "l"(a3));
    }

    // --- coalesced output: thread t writes floats [t*8, t*8+8) of this point ---
    ulonglong2* op = (ulonglong2*)(out + (size_t)p * (C_ * CMID_) + (size_t)t * 8);
    op[0] = make_ulonglong2(a0, a1);
    op[1] = make_ulonglong2(a2, a3);
}

extern "C" void kernel_launch(void* const* d_in, const int* in_sizes, int n_in,
                              void* d_out, int out_size) {
    const float* feat = (const float*)d_in[0];
    const void*  inds = d_in[1];
    const float* guid = (const float*)d_in[2];
    const float* wn   = (const float*)d_in[3];
    float* out = (float*)d_out;

    detect_idx_kernel<<<1, 32>>>((const unsigned int*)inds);
    pcf_kernel<<<B_ * M_, 128>>>(feat, inds, guid, wn, out);
}

// round 2
// speedup vs baseline: 1.0960x; 1.0960x over previous
#include <cuda_runtime.h>
#include <cstdint>

// Problem shape (fixed for this dataset entry)
#define B_    2
#define N_    50000
#define C_    64
#define M_    50000
#define K_    16
#define H_    8
#define CMID_ 16

// Runtime-detected index width flag (int64 vs int32), set by detect kernel.
__device__ int g_idx_is64;

__global__ void detect_idx_kernel(const unsigned int* __restrict__ w) {
    if (threadIdx.x == 0 && blockIdx.x == 0) {
        int is64 = 1;
        #pragma unroll 1
        for (int i = 0; i < 256; i++) {
            if (w[2 * i + 1] != 0u) { is64 = 0; break; }
        }
        g_idx_is64 = is64;
    }
}

// One WARP per point; 4 points per 128-thread CTA.
// Lane mapping: c4 = lane & 15 (channel quad), wh = lane >> 4 (w half).
// Thread tile: 4 channels x 8 w = 32 outputs held as 16 packed f32x2 accums.
// Per k: 1 coalesced LDG.128 of the gathered feature row (L2-resident),
//        1 scalar LDS (guidance, broadcast), 2 LDS.128 (weightnet row),
//        4 FMUL + 4 pack + 16 fma.rn.f32x2.
__global__ void __launch_bounds__(128)
pcf_kernel(const float* __restrict__ feat,
           const void*  __restrict__ inds_raw,
           const float* __restrict__ guid,
           const float* __restrict__ wn,
           float* __restrict__ out)
{
    __shared__ __align__(16) float swn[4][K_ * CMID_];  // 4 x 1KB
    __shared__ __align__(16) float sgd[4][K_ * H_];     // 4 x 512B
    __shared__ int sidx[4][K_];

    const int wid  = threadIdx.x >> 5;
    const int lane = threadIdx.x & 31;
    const int p    = blockIdx.x * 4 + wid;      // point id in [0, B*M)
    const int b    = (p >= M_) ? 1 : 0;
    const int c4   = lane & 15;                 // channel quad 0..15
    const int wh   = lane >> 4;                 // w half 0..1

    // ---- per-warp staging of weightnet, guidance, indices ----
    {
        const float4* wsrc = (const float4*)(wn + (size_t)p * (K_ * CMID_));
        float4* wdst = (float4*)(swn[wid]);
        wdst[lane]      = wsrc[lane];
        wdst[lane + 32] = wsrc[lane + 32];
        ((float4*)(sgd[wid]))[lane] = ((const float4*)(guid + (size_t)p * (K_ * H_)))[lane];
        if (lane < K_) {
            long long idx;
            if (g_idx_is64) idx = ((const long long*)inds_raw)[(size_t)p * K_ + lane];
            else            idx = (long long)((const int*)inds_raw)[(size_t)p * K_ + lane];
            sidx[wid][lane] = (int)idx;
        }
    }
    __syncwarp();

    const float* fb = feat + (size_t)b * ((size_t)N_ * C_);

    unsigned long long acc[16];
    #pragma unroll
    for (int i = 0; i < 16; i++) acc[i] = 0ull;

    #pragma unroll 4
    for (int k = 0; k < K_; k++) {
        const int ix = sidx[wid][k];
        float4 f = ((const float4*)(fb + (size_t)ix * C_))[c4];   // coalesced 256B/row
        const float g = sgd[wid][k * H_ + (c4 >> 1)];             // head for channels 4*c4..
        f.x *= g; f.y *= g; f.z *= g; f.w *= g;

        unsigned long long ff0, ff1, ff2, ff3;
        asm("mov.b64 %0, {%1, %1};" : "=l"(ff0) : "f"(f.x));
        asm("mov.b64 %0, {%1, %1};" : "=l"(ff1) : "f"(f.y));
        asm("mov.b64 %0, {%1, %1};" : "=l"(ff2) : "f"(f.z));
        asm("mov.b64 %0, {%1, %1};" : "=l"(ff3) : "f"(f.w));

        const ulonglong2* row = (const ulonglong2*)(swn[wid] + k * CMID_ + wh * 8);
        ulonglong2 W0 = row[0];   // w = wh*8 + 0..3
        ulonglong2 W1 = row[1];   // w = wh*8 + 4..7

        asm("fma.rn.f32x2 %0, %1, %2, %3;" : "=l"(acc[ 0]) : "l"(ff0), "l"(W0.x), "l"(acc[ 0]));
        asm("fma.rn.f32x2 %0, %1, %2, %3;" : "=l"(acc[ 1]) : "l"(ff0), "l"(W0.y), "l"(acc[ 1]));
        asm("fma.rn.f32x2 %0, %1, %2, %3;" : "=l"(acc[ 2]) : "l"(ff0), "l"(W1.x), "l"(acc[ 2]));
        asm("fma.rn.f32x2 %0, %1, %2, %3;" : "=l"(acc[ 3]) : "l"(ff0), "l"(W1.y), "l"(acc[ 3]));
        asm("fma.rn.f32x2 %0, %1, %2, %3;" : "=l"(acc[ 4]) : "l"(ff1), "l"(W0.x), "l"(acc[ 4]));
        asm("fma.rn.f32x2 %0, %1, %2, %3;" : "=l"(acc[ 5]) : "l"(ff1), "l"(W0.y), "l"(acc[ 5]));
        asm("fma.rn.f32x2 %0, %1, %2, %3;" : "=l"(acc[ 6]) : "l"(ff1), "l"(W1.x), "l"(acc[ 6]));
        asm("fma.rn.f32x2 %0, %1, %2, %3;" : "=l"(acc[ 7]) : "l"(ff1), "l"(W1.y), "l"(acc[ 7]));
        asm("fma.rn.f32x2 %0, %1, %2, %3;" : "=l"(acc[ 8]) : "l"(ff2), "l"(W0.x), "l"(acc[ 8]));
        asm("fma.rn.f32x2 %0, %1, %2, %3;" : "=l"(acc[ 9]) : "l"(ff2), "l"(W0.y), "l"(acc[ 9]));
        asm("fma.rn.f32x2 %0, %1, %2, %3;" : "=l"(acc[10]) : "l"(ff2), "l"(W1.x), "l"(acc[10]));
        asm("fma.rn.f32x2 %0, %1, %2, %3;" : "=l"(acc[11]) : "l"(ff2), "l"(W1.y), "l"(acc[11]));
        asm("fma.rn.f32x2 %0, %1, %2, %3;" : "=l"(acc[12]) : "l"(ff3), "l"(W0.x), "l"(acc[12]));
        asm("fma.rn.f32x2 %0, %1, %2, %3;" : "=l"(acc[13]) : "l"(ff3), "l"(W0.y), "l"(acc[13]));
        asm("fma.rn.f32x2 %0, %1, %2, %3;" : "=l"(acc[14]) : "l"(ff3), "l"(W1.x), "l"(acc[14]));
        asm("fma.rn.f32x2 %0, %1, %2, %3;" : "=l"(acc[15]) : "l"(ff3), "l"(W1.y), "l"(acc[15]));
    }

    // ---- output: thread owns rows c = 4*c4 .. 4*c4+3, w in [wh*8, wh*8+8) ----
    float* op = out + (size_t)p * (C_ * CMID_) + (size_t)(c4 * 4) * CMID_ + wh * 8;
    #pragma unroll
    for (int cc = 0; cc < 4; cc++) {
        ((ulonglong2*)(op + cc * CMID_))[0] = make_ulonglong2(acc[cc * 4 + 0], acc[cc * 4 + 1]);
        ((ulonglong2*)(op + cc * CMID_ + 4))[0] = make_ulonglong2(acc[cc * 4 + 2], acc[cc * 4 + 3]);
    }
}

extern "C" void kernel_launch(void* const* d_in, const int* in_sizes, int n_in,
                              void* d_out, int out_size) {
    const float* feat = (const float*)d_in[0];
    const void*  inds = d_in[1];
    const float* guid = (const float*)d_in[2];
    const float* wn   = (const float*)d_in[3];
    float* out = (float*)d_out;

    detect_idx_kernel<<<1, 32>>>((const unsigned int*)inds);
    pcf_kernel<<<(B_ * M_) / 4, 128>>>(feat, inds, guid, wn, out);
}

// round 3
// speedup vs baseline: 1.1980x; 1.0931x over previous
#include <cuda_runtime.h>
#include <cstdint>

// Problem shape (fixed for this dataset entry)
#define B_    2
#define N_    50000
#define C_    64
#define M_    50000
#define K_    16
#define H_    8
#define CMID_ 16
#define PF    4    // gather prefetch depth

// Runtime-detected index width flag (int64 vs int32), set by detect kernel.
__device__ int g_idx_is64;

__global__ void detect_idx_kernel(const unsigned int* __restrict__ w) {
    if (threadIdx.x == 0 && blockIdx.x == 0) {
        int is64 = 1;
        #pragma unroll 1
        for (int i = 0; i < 256; i++) {
            if (w[2 * i + 1] != 0u) { is64 = 0; break; }
        }
        g_idx_is64 = is64;
    }
}

// One WARP per point; 4 points per 128-thread CTA.
// Lane l owns channels {2l, 2l+1} (zero-duplication gather: one LDG.64 per k
// covers the full 256B feature row exactly once per warp) and ALL 16 w.
// Accumulators: 2 channels x 8 w-pairs = 16 packed f32x2.
//   multiplicand {W[k][2j], W[k][2j+1]} comes packed straight out of 4
//   fully-uniform (broadcast) LDS.128 per k — no dup movs on the W side.
//   multiplier {g*f, g*f} needs only 2 FMUL + 2 dup-movs per k.
// Gather LDG.64s run through a 4-deep software prefetch pipeline (MLP=4).
__global__ void __launch_bounds__(128)
pcf_kernel(const float* __restrict__ feat,
           const void*  __restrict__ inds_raw,
           const float* __restrict__ guid,
           const float* __restrict__ wn,
           float* __restrict__ out)
{
    __shared__ __align__(16) float swn[4][K_ * CMID_];  // 4 x 1KB  weightnet
    __shared__ __align__(16) float sgd[4][K_ * H_];     // 4 x 512B guidance
    __shared__ int sidx[4][K_];

    const int wid  = threadIdx.x >> 5;
    const int lane = threadIdx.x & 31;
    const int p    = blockIdx.x * 4 + wid;      // point id in [0, B*M)
    const int b    = (p >= M_) ? 1 : 0;
    const int hd   = lane >> 2;                 // head of channels {2l,2l+1}

    // ---- per-warp staging: weightnet (1KB), guidance (512B), indices ----
    {
        const float4* wsrc = (const float4*)(wn + (size_t)p * (K_ * CMID_));
        float4* wdst = (float4*)(swn[wid]);
        wdst[lane]      = wsrc[lane];
        wdst[lane + 32] = wsrc[lane + 32];
        ((float4*)(sgd[wid]))[lane] = ((const float4*)(guid + (size_t)p * (K_ * H_)))[lane];
        if (lane < K_) {
            long long idx;
            if (g_idx_is64) idx = ((const long long*)inds_raw)[(size_t)p * K_ + lane];
            else            idx = (long long)((const int*)inds_raw)[(size_t)p * K_ + lane];
            sidx[wid][lane] = (int)idx;
        }
    }
    __syncwarp();

    // lane-fixed channel offset: feature row base + channel 2*lane
    const float* fb = feat + (size_t)b * ((size_t)N_ * C_) + 2 * lane;

    // ---- prefetch pipeline for the gather (zero-dup LDG.64) ----
    float2 gbuf[PF];
    #pragma unroll
    for (int i = 0; i < PF; i++)
        gbuf[i] = *(const float2*)(fb + (size_t)sidx[wid][i] * C_);

    unsigned long long acc[16];
    #pragma unroll
    for (int i = 0; i < 16; i++) acc[i] = 0ull;

    #pragma unroll
    for (int k = 0; k < K_; k++) {
        float2 f = gbuf[k % PF];
        if (k + PF < K_)
            gbuf[k % PF] = *(const float2*)(fb + (size_t)sidx[wid][k + PF] * C_);

        const float g = sgd[wid][k * H_ + hd];  // broadcast (8 distinct words)
        const float s0 = f.x * g;
        const float s1 = f.y * g;
        unsigned long long g0, g1;
        asm("mov.b64 %0, {%1, %1};" : "=l"(g0) : "f"(s0));
        asm("mov.b64 %0, {%1, %1};" : "=l"(g1) : "f"(s1));

        // W row k: 16 floats = 4 uniform LDS.128 -> 8 packed {w2j, w2j+1}
        const ulonglong2* wr = (const ulonglong2*)(swn[wid] + k * CMID_);
        ulonglong2 A = wr[0];   // {w0w1, w2w3}
        ulonglong2 Bv = wr[1];  // {w4w5, w6w7}
        ulonglong2 Cv = wr[2];  // {w8w9, w10w11}
        ulonglong2 Dv = wr[3];  // {w12w13, w14w15}

        asm("fma.rn.f32x2 %0, %1, %2, %3;" : "=l"(acc[ 0]) : "l"(g0), "l"(A.x),  "l"(acc[ 0]));
        asm("fma.rn.f32x2 %0, %1, %2, %3;" : "=l"(acc[ 1]) : "l"(g0), "l"(A.y),  "l"(acc[ 1]));
        asm("fma.rn.f32x2 %0, %1, %2, %3;" : "=l"(acc[ 2]) : "l"(g0), "l"(Bv.x), "l"(acc[ 2]));
        asm("fma.rn.f32x2 %0, %1, %2, %3;" : "=l"(acc[ 3]) : "l"(g0), "l"(Bv.y), "l"(acc[ 3]));
        asm("fma.rn.f32x2 %0, %1, %2, %3;" : "=l"(acc[ 4]) : "l"(g0), "l"(Cv.x), "l"(acc[ 4]));
        asm("fma.rn.f32x2 %0, %1, %2, %3;" : "=l"(acc[ 5]) : "l"(g0), "l"(Cv.y), "l"(acc[ 5]));
        asm("fma.rn.f32x2 %0, %1, %2, %3;" : "=l"(acc[ 6]) : "l"(g0), "l"(Dv.x), "l"(acc[ 6]));
        asm("fma.rn.f32x2 %0, %1, %2, %3;" : "=l"(acc[ 7]) : "l"(g0), "l"(Dv.y), "l"(acc[ 7]));
        asm("fma.rn.f32x2 %0, %1, %2, %3;" : "=l"(acc[ 8]) : "l"(g1), "l"(A.x),  "l"(acc[ 8]));
        asm("fma.rn.f32x2 %0, %1, %2, %3;" : "=l"(acc[ 9]) : "l"(g1), "l"(A.y),  "l"(acc[ 9]));
        asm("fma.rn.f32x2 %0, %1, %2, %3;" : "=l"(acc[10]) : "l"(g1), "l"(Bv.x), "l"(acc[10]));
        asm("fma.rn.f32x2 %0, %1, %2, %3;" : "=l"(acc[11]) : "l"(g1), "l"(Bv.y), "l"(acc[11]));
        asm("fma.rn.f32x2 %0, %1, %2, %3;" : "=l"(acc[12]) : "l"(g1), "l"(Cv.x), "l"(acc[12]));
        asm("fma.rn.f32x2 %0, %1, %2, %3;" : "=l"(acc[13]) : "l"(g1), "l"(Cv.y), "l"(acc[13]));
        asm("fma.rn.f32x2 %0, %1, %2, %3;" : "=l"(acc[14]) : "l"(g1), "l"(Dv.x), "l"(acc[14]));
        asm("fma.rn.f32x2 %0, %1, %2, %3;" : "=l"(acc[15]) : "l"(g1), "l"(Dv.y), "l"(acc[15]));
    }

    // ---- output: rows c0 = 2*lane (acc[0..7]) and c1 = 2*lane+1 (acc[8..15])
    float* o = out + (size_t)p * (C_ * CMID_) + (size_t)lane * 32;
    ulonglong2* o0 = (ulonglong2*)o;          // row c0: 16 floats
    o0[0] = make_ulonglong2(acc[0], acc[1]);
    o0[1] = make_ulonglong2(acc[2], acc[3]);
    o0[2] = make_ulonglong2(acc[4], acc[5]);
    o0[3] = make_ulonglong2(acc[6], acc[7]);
    ulonglong2* o1 = (ulonglong2*)(o + CMID_); // row c1: 16 floats
    o1[0] = make_ulonglong2(acc[ 8], acc[ 9]);
    o1[1] = make_ulonglong2(acc[10], acc[11]);
    o1[2] = make_ulonglong2(acc[12], acc[13]);
    o1[3] = make_ulonglong2(acc[14], acc[15]);
}

extern "C" void kernel_launch(void* const* d_in, const int* in_sizes, int n_in,
                              void* d_out, int out_size) {
    const float* feat = (const float*)d_in[0];
    const void*  inds = d_in[1];
    const float* guid = (const float*)d_in[2];
    const float* wn   = (const float*)d_in[3];
    float* out = (float*)d_out;

    detect_idx_kernel<<<1, 32>>>((const unsigned int*)inds);
    pcf_kernel<<<(B_ * M_) / 4, 128>>>(feat, inds, guid, wn, out);
}